// round 8
// baseline (speedup 1.0000x reference)
#include <cuda_runtime.h>
#include <math.h>

#define T_STEPS 512
#define BS      256
#define IC      128
#define HC      256
#define G4      1024   // 4*HC
#define NB      128    // persistent CTAs (1/SM, all co-resident: 128 <= 148 SMs)
#define NT      128    // threads per persistent CTA

// ---------------- scratch (static device globals; no runtime allocation) ----------------
__device__ float g_gin [(size_t)T_STEPS * BS * G4];  // per-layer input projections (+biases)
__device__ float g_seq0[(size_t)T_STEPS * BS * HC];  // layer-0 output sequence
__device__ float g_h[BS * HC];
__device__ float g_c[BS * HC];
__device__ float g_gates[BS * G4];
__device__ float g_u[BS];
__device__ float g_du[BS];
__device__ int   g_skip[BS];
__device__ unsigned g_count;                          // grid barrier counter (monotonic)

// ---------------------------------------------------------------------------------------
// XLA-exact elementwise math (EmitFastTanh + LogisticExpander).
// ---------------------------------------------------------------------------------------
__device__ __forceinline__ float tanh_xla(float x)
{
    float ax = fabsf(x);
    float xc = fmaxf(-9.0f, fminf(x, 9.0f));
    float x2 = __fmul_rn(xc, xc);
    float p = -2.76076847742355e-16f;
    p = __fadd_rn(__fmul_rn(p, x2),  2.00018790482477e-13f);
    p = __fadd_rn(__fmul_rn(p, x2), -8.60467152213735e-11f);
    p = __fadd_rn(__fmul_rn(p, x2),  5.12229709037114e-08f);
    p = __fadd_rn(__fmul_rn(p, x2),  1.48572235717979e-05f);
    p = __fadd_rn(__fmul_rn(p, x2),  6.37261928875436e-04f);
    p = __fadd_rn(__fmul_rn(p, x2),  4.89352455891786e-03f);
    p = __fmul_rn(p, xc);
    float q =  1.19825839466702e-06f;
    q = __fadd_rn(__fmul_rn(q, x2),  1.18534705686654e-04f);
    q = __fadd_rn(__fmul_rn(q, x2),  2.26843463243900e-03f);
    q = __fadd_rn(__fmul_rn(q, x2),  4.89352518554385e-03f);
    float r = __fdiv_rn(p, q);
    return (ax < 0.0004f) ? x : r;
}

__device__ __forceinline__ float logi_xla(float x)
{
    float t = tanh_xla(__fmul_rn(0.5f, x));
    return __fadd_rn(0.5f, __fmul_rn(0.5f, t));
}

// Monotonic-counter grid barrier (g_count zeroed before each launch).
// VOLATILE poll (cannot be hoisted/CSE'd) + nanosleep backoff — exactly the
// formulation that executed successfully in earlier rounds.
__device__ __forceinline__ void grid_sync(unsigned& nbar)
{
    __syncthreads();
    if (threadIdx.x == 0) {
        __threadfence();
        nbar += 1;
        const unsigned target = nbar * NB;
        atomicAdd(&g_count, 1u);
        while (*(volatile unsigned*)&g_count < target) { __nanosleep(64); }
    }
    __syncthreads();
}

// ---------------------------------------------------------------------------------------
// Input projection: g_gin[m][n] = sum_k A[m][k]*W[n][k] + b0[n] + b1[n]
// Ascending-k single-accumulator FMA chain per output element.
// ---------------------------------------------------------------------------------------
__global__ __launch_bounds__(256) void inproj_kernel(
    const float* __restrict__ xin, int useSeq0, int K,
    const float* __restrict__ Wih,
    const float* __restrict__ b0, const float* __restrict__ b1)
{
    const float* A = useSeq0 ? g_seq0 : xin;
    __shared__ float As[8][132];
    __shared__ float Bs[8][132];

    const int tid = threadIdx.x;
    const int n0  = blockIdx.x << 7;
    const int m0  = blockIdx.y << 7;
    const int ty  = tid >> 4;          // 0..15 : rows ty*8..+7
    const int tx  = tid & 15;          // 0..15 : cols tx*8..+7
    const int r   = tid >> 1;          // 0..127
    const int kc  = (tid & 1) << 2;    // 0 or 4

    const float* Ap = A   + (size_t)(m0 + r) * K + kc;
    const float* Wp = Wih + (size_t)(n0 + r) * K + kc;

    float acc[8][8] = {};
    const int nch = K >> 3;
    float4 pa = __ldg((const float4*)Ap);
    float4 pw = __ldg((const float4*)Wp);

    for (int ch = 0; ch < nch; ch++) {
        As[kc + 0][r] = pa.x; As[kc + 1][r] = pa.y; As[kc + 2][r] = pa.z; As[kc + 3][r] = pa.w;
        Bs[kc + 0][r] = pw.x; Bs[kc + 1][r] = pw.y; Bs[kc + 2][r] = pw.z; Bs[kc + 3][r] = pw.w;
        __syncthreads();
        if (ch + 1 < nch) {
            pa = __ldg((const float4*)(Ap + (ch + 1) * 8));
            pw = __ldg((const float4*)(Wp + (ch + 1) * 8));
        }
#pragma unroll
        for (int k = 0; k < 8; k++) {        // ascending k
            float4 a0 = *(const float4*)&As[k][ty << 3];
            float4 a1 = *(const float4*)&As[k][(ty << 3) + 4];
            float4 w0 = *(const float4*)&Bs[k][tx << 3];
            float4 w1 = *(const float4*)&Bs[k][(tx << 3) + 4];
            float ar[8] = {a0.x, a0.y, a0.z, a0.w, a1.x, a1.y, a1.z, a1.w};
            float br[8] = {w0.x, w0.y, w0.z, w0.w, w1.x, w1.y, w1.z, w1.w};
#pragma unroll
            for (int i = 0; i < 8; i++)
#pragma unroll
                for (int j = 0; j < 8; j++)
                    acc[i][j] = fmaf(ar[i], br[j], acc[i][j]);
        }
        __syncthreads();
    }

    const int col = n0 + (tx << 3);
    float bias[8];
#pragma unroll
    for (int j = 0; j < 8; j++) bias[j] = __fadd_rn(b0[col + j], b1[col + j]);
#pragma unroll
    for (int i = 0; i < 8; i++) {
        size_t row = (size_t)m0 + (ty << 3) + i;
        float* o = g_gin + row * G4 + col;
#pragma unroll
        for (int j = 0; j < 8; j++) o[j] = __fadd_rn(acc[i][j], bias[j]);
    }
}

// ---------------------------------------------------------------------------------------
// Persistent per-layer recurrence kernel. 128 CTAs x 128 threads, 1 CTA/SM.
// ---------------------------------------------------------------------------------------
#define WS_ELEMS (256 * 68)
#define HS_ELEMS (256 * 36)
#define DYN_SMEM ((WS_ELEMS + HS_ELEMS) * 4)

__global__ __launch_bounds__(NT, 1) void layer_kernel(
    const float* __restrict__ W,                   // Whh [1024][256]
    const float* __restrict__ lw, const float* __restrict__ lb,
    float* __restrict__ seq_out, int to_seq0)
{
    extern __shared__ float sm[];
    float* Ws = sm;               // [k][n] 256 x 68 (pad)
    float* Hs = sm + WS_ELEMS;    // [k][m] 256 x 36 (pad)
    __shared__ float snc[2][256]; // staged nc_n for the du dot
    __shared__ float slw[256];

    const int tid  = threadIdx.x;
    const int bid  = blockIdx.x;
    const int n0   = (bid & 15) * 64;
    const int m0   = (bid >> 4) * 32;
    const int ty   = tid >> 4;          // 0..7  rows ty*4..+3
    const int tx   = tid & 15;          // 0..15 cols tx*4..+3
    const int wid  = tid >> 5;
    const int lane = tid & 31;

    if (tid < 128) { slw[tid] = lw[tid]; slw[tid + 128] = lw[tid + 128]; }
    const float lb0v = lb[0];
    for (int i = tid; i < 64 * 64; i += NT) {
        int rr = i >> 6;
        int k4 = (i & 63) << 2;
        float4 v = __ldcg((const float4*)(W + (size_t)(n0 + rr) * HC + k4));
        Ws[(k4 + 0) * 68 + rr] = v.x; Ws[(k4 + 1) * 68 + rr] = v.y;
        Ws[(k4 + 2) * 68 + rr] = v.z; Ws[(k4 + 3) * 68 + rr] = v.w;
    }

    const int pb = 2 * bid + (wid >> 1);       // this CTA's two pointwise rows
    const int q  = ((wid & 1) << 5) + lane;    // 0..63

    unsigned nbar = 0;

    for (int t = 0; t < T_STEPS; t++) {
        float4 pg[4];
        {
            const float* gp = g_gin + ((size_t)t * BS + m0 + (ty << 2)) * G4 + n0 + (tx << 2);
#pragma unroll
            for (int i = 0; i < 4; i++) pg[i] = __ldcg((const float4*)(gp + (size_t)i * G4));
        }

        grid_sync(nbar);   // h(t) ready

        for (int i = tid; i < 32 * 64; i += NT) {
            int rr = i >> 6;
            int k4 = (i & 63) << 2;
            float4 v = __ldcg((const float4*)(g_h + (m0 + rr) * HC + k4));
            Hs[(k4 + 0) * 36 + rr] = v.x; Hs[(k4 + 1) * 36 + rr] = v.y;
            Hs[(k4 + 2) * 36 + rr] = v.z; Hs[(k4 + 3) * 36 + rr] = v.w;
        }
        __syncthreads();

        const int r0 = m0 + (wid << 3);
        int fl = (lane < 8) ? __ldcg(&g_skip[r0 + lane]) : 1;
        const bool allskip = __all_sync(0xffffffffu, fl != 0);

        if (!allskip) {
            float acc[4][4] = {};
            const float* hp = &Hs[ty << 2];
            const float* wp = &Ws[tx << 2];
#pragma unroll 8
            for (int k = 0; k < HC; k++) {           // strictly ascending k
                float4 a = *(const float4*)(hp + k * 36);
                float4 b = *(const float4*)(wp + k * 68);
                acc[0][0] = fmaf(a.x, b.x, acc[0][0]); acc[0][1] = fmaf(a.x, b.y, acc[0][1]);
                acc[0][2] = fmaf(a.x, b.z, acc[0][2]); acc[0][3] = fmaf(a.x, b.w, acc[0][3]);
                acc[1][0] = fmaf(a.y, b.x, acc[1][0]); acc[1][1] = fmaf(a.y, b.y, acc[1][1]);
                acc[1][2] = fmaf(a.y, b.z, acc[1][2]); acc[1][3] = fmaf(a.y, b.w, acc[1][3]);
                acc[2][0] = fmaf(a.z, b.x, acc[2][0]); acc[2][1] = fmaf(a.z, b.y, acc[2][1]);
                acc[2][2] = fmaf(a.z, b.z, acc[2][2]); acc[2][3] = fmaf(a.z, b.w, acc[2][3]);
                acc[3][0] = fmaf(a.w, b.x, acc[3][0]); acc[3][1] = fmaf(a.w, b.y, acc[3][1]);
                acc[3][2] = fmaf(a.w, b.z, acc[3][2]); acc[3][3] = fmaf(a.w, b.w, acc[3][3]);
            }
#pragma unroll
            for (int i = 0; i < 4; i++) {
                float4 v = make_float4(__fadd_rn(acc[i][0], pg[i].x), __fadd_rn(acc[i][1], pg[i].y),
                                       __fadd_rn(acc[i][2], pg[i].z), __fadd_rn(acc[i][3], pg[i].w));
                __stcg((float4*)(g_gates + (size_t)(m0 + (ty << 2) + i) * G4 + n0 + (tx << 2)), v);
            }
        }

        grid_sync(nbar);   // gates ready

        // ---- pointwise phase: this CTA's two rows ----
        {
            const float uo  = g_u[pb];
            const float duo = g_du[pb];
            const int   m   = g_skip[pb];
            const float bu  = rintf(uo);                       // jnp.round (half-to-even)
            const float omb = __fsub_rn(1.0f, bu);

            float* hrow = g_h + pb * HC;
            float* crow = g_c + pb * HC;
            float* drow = (to_seq0 ? g_seq0 : seq_out) + (size_t)t * BS * HC + pb * HC;

            if (!m) {
                const float* grow = g_gates + (size_t)pb * G4;
#pragma unroll
                for (int s = 0; s < 4; s++) {
                    const int j = q + (s << 6);
                    float gi = __ldcg(grow + j);
                    float gf = __ldcg(grow + HC + j);
                    float gg = __ldcg(grow + 2 * HC + j);
                    float go = __ldcg(grow + 3 * HC + j);
                    float co = crow[j];
                    float cc = __fadd_rn(__fmul_rn(logi_xla(gf), co),
                                         __fmul_rn(logi_xla(gi), tanh_xla(gg)));
                    float ch = __fmul_rn(logi_xla(go), tanh_xla(cc));
                    float nc = __fmul_rn(cc, bu);
                    float nh = __fmul_rn(ch, bu);
                    __stcg(hrow + j, nh);
                    __stcg(crow + j, nc);
                    __stcg(drow + j, nh);
                    snc[wid >> 1][j] = nc;
                }
            } else {
#pragma unroll
                for (int s = 0; s < 4; s++) {
                    const int j = q + (s << 6);
                    float nh = __fmul_rn(hrow[j], omb);
                    float nc = __fmul_rn(crow[j], omb);
                    __stcg(hrow + j, nh);
                    __stcg(crow + j, nc);
                    __stcg(drow + j, nh);
                }
            }
            __syncthreads();

            if (lane == 0 && !(wid & 1)) {
                float nu, ndu;
                if (!m) {
                    // Eigen-gemv order: 4 strided lane accumulators + pairwise sum.
                    const float* v = snc[wid >> 1];
                    float a0 = 0.0f, a1 = 0.0f, a2 = 0.0f, a3 = 0.0f;
                    for (int k = 0; k < HC; k += 4) {
                        a0 = fmaf(v[k + 0], slw[k + 0], a0);
                        a1 = fmaf(v[k + 1], slw[k + 1], a1);
                        a2 = fmaf(v[k + 2], slw[k + 2], a2);
                        a3 = fmaf(v[k + 3], slw[k + 3], a3);
                    }
                    float dot = __fadd_rn(__fadd_rn(a0, a1), __fadd_rn(a2, a3));
                    float dn = logi_xla(__fadd_rn(dot, lb0v));
                    nu = __fmul_rn(dn, bu); ndu = dn;
                } else {
                    nu = __fmul_rn(fminf(fmaxf(__fadd_rn(uo, duo), 0.0f), 1.0f), omb);
                    ndu = duo;
                }
                g_u[pb]  = nu;
                g_du[pb] = ndu;
                __stcg(&g_skip[pb], ((__fsub_rn(ceilf(__fdiv_rn(0.5f, nu)), 1.0f)) > 0.0f) ? 1 : 0);
            }
        }
    }
}

// ---------------------------------------------------------------------------------------
// Reference semantics: h, c, u re-initialize per layer; skip and du CARRY across layers.
// ---------------------------------------------------------------------------------------
__global__ void init_full_kernel()
{
    int i = blockIdx.x * blockDim.x + threadIdx.x;
    if (i < BS * HC) { g_h[i] = 0.0f; g_c[i] = 0.0f; }
    if (i < BS)      { g_u[i] = 1.0f; g_du[i] = 0.0f; g_skip[i] = 0; }
    if (i == 0)      { g_count = 0u; }
}

__global__ void init_partial_kernel()   // keep skip/du
{
    int i = blockIdx.x * blockDim.x + threadIdx.x;
    if (i < BS * HC) { g_h[i] = 0.0f; g_c[i] = 0.0f; }
    if (i < BS)      { g_u[i] = 1.0f; }
    if (i == 0)      { g_count = 0u; }
}

__global__ void copy_state_kernel(float* __restrict__ dh, float* __restrict__ dc)
{
    int i = blockIdx.x * blockDim.x + threadIdx.x;
    if (i < BS * HC) { dh[i] = g_h[i]; dc[i] = g_c[i]; }
}

// ---------------------------------------------------------------------------------------
extern "C" void kernel_launch(void* const* d_in, const int* in_sizes, int n_in,
                              void* d_out, int out_size)
{
    const float* x    = (const float*)d_in[0];
    const float* Wih0 = (const float*)d_in[1];
    const float* Whh0 = (const float*)d_in[2];
    const float* bih0 = (const float*)d_in[3];
    const float* bhh0 = (const float*)d_in[4];
    const float* lw0  = (const float*)d_in[5];
    const float* lb0  = (const float*)d_in[6];
    const float* Wih1 = (const float*)d_in[7];
    const float* Whh1 = (const float*)d_in[8];
    const float* bih1 = (const float*)d_in[9];
    const float* bhh1 = (const float*)d_in[10];
    const float* lw1  = (const float*)d_in[11];
    const float* lb1  = (const float*)d_in[12];

    float* out   = (float*)d_out;                         // [T, BS, HC]
    float* outHs = out + (size_t)T_STEPS * BS * HC;       // [2, BS, HC]
    float* outCs = outHs + 2 * BS * HC;                   // [2, BS, HC]

    cudaFuncSetAttribute(layer_kernel, cudaFuncAttributeMaxDynamicSharedMemorySize, DYN_SMEM);

    dim3 proj_grid(G4 / 128, (T_STEPS * BS) / 128);       // (8, 1024)

    // ---- layer 0 ----
    inproj_kernel<<<proj_grid, 256>>>(x, 0, IC, Wih0, bih0, bhh0);
    init_full_kernel<<<256, 256>>>();
    layer_kernel<<<NB, NT, DYN_SMEM>>>(Whh0, lw0, lb0, nullptr, 1);
    copy_state_kernel<<<256, 256>>>(outHs, outCs);

    // ---- layer 1 ----
    inproj_kernel<<<proj_grid, 256>>>(nullptr, 1, HC, Wih1, bih1, bhh1);
    init_partial_kernel<<<256, 256>>>();                  // skip/du carry across layers
    layer_kernel<<<NB, NT, DYN_SMEM>>>(Whh1, lw1, lb1, out, 0);
    copy_state_kernel<<<256, 256>>>(outHs + BS * HC, outCs + BS * HC);
}

// round 9
// speedup vs baseline: 1.0381x; 1.0381x over previous
#include <cuda_runtime.h>
#include <math.h>

#define T_STEPS 512
#define BS      256
#define IC      128
#define HC      256
#define G4      1024   // 4*HC
#define NB      128    // persistent CTAs = 8 m-tiles x 16 n-groups (1/SM, co-resident)
#define NT      128    // threads per persistent CTA

// ---------------- scratch (static device globals; no runtime allocation) ----------------
__device__ float g_gin [(size_t)T_STEPS * BS * G4];  // per-layer input projections (+biases)
__device__ float g_seq0[(size_t)T_STEPS * BS * HC];  // layer-0 output sequence
__device__ float g_h  [2][BS * HC];                  // h double-buffered by step parity
__device__ float g_ncb[2][BS * HC];                  // nc (for du dot) double-buffered
__device__ float g_du[BS];                           // carried across layers
__device__ int   g_skip[BS];                         // carried across layers
__device__ unsigned g_count;                         // grid barrier counter (monotonic)

// ---------------------------------------------------------------------------------------
// XLA-exact elementwise math (EmitFastTanh + LogisticExpander).
// ---------------------------------------------------------------------------------------
__device__ __forceinline__ float tanh_xla(float x)
{
    float ax = fabsf(x);
    float xc = fmaxf(-9.0f, fminf(x, 9.0f));
    float x2 = __fmul_rn(xc, xc);
    float p = -2.76076847742355e-16f;
    p = __fadd_rn(__fmul_rn(p, x2),  2.00018790482477e-13f);
    p = __fadd_rn(__fmul_rn(p, x2), -8.60467152213735e-11f);
    p = __fadd_rn(__fmul_rn(p, x2),  5.12229709037114e-08f);
    p = __fadd_rn(__fmul_rn(p, x2),  1.48572235717979e-05f);
    p = __fadd_rn(__fmul_rn(p, x2),  6.37261928875436e-04f);
    p = __fadd_rn(__fmul_rn(p, x2),  4.89352455891786e-03f);
    p = __fmul_rn(p, xc);
    float q =  1.19825839466702e-06f;
    q = __fadd_rn(__fmul_rn(q, x2),  1.18534705686654e-04f);
    q = __fadd_rn(__fmul_rn(q, x2),  2.26843463243900e-03f);
    q = __fadd_rn(__fmul_rn(q, x2),  4.89352518554385e-03f);
    float r = __fdiv_rn(p, q);
    return (ax < 0.0004f) ? x : r;
}

__device__ __forceinline__ float logi_xla(float x)
{
    float t = tanh_xla(__fmul_rn(0.5f, x));
    return __fadd_rn(0.5f, __fmul_rn(0.5f, t));
}

// Monotonic-counter grid barrier — proven formulation (volatile poll + nanosleep).
__device__ __forceinline__ void grid_sync(unsigned& nbar)
{
    __syncthreads();
    if (threadIdx.x == 0) {
        __threadfence();
        nbar += 1;
        const unsigned target = nbar * NB;
        atomicAdd(&g_count, 1u);
        while (*(volatile unsigned*)&g_count < target) { __nanosleep(64); }
    }
    __syncthreads();
}

// ---------------------------------------------------------------------------------------
// Input projection: g_gin[m][n] = sum_k A[m][k]*W[n][k] + b0[n] + b1[n]
// Ascending-k single-accumulator FMA chain per output element. (unchanged — passed)
// ---------------------------------------------------------------------------------------
__global__ __launch_bounds__(256) void inproj_kernel(
    const float* __restrict__ xin, int useSeq0, int K,
    const float* __restrict__ Wih,
    const float* __restrict__ b0, const float* __restrict__ b1)
{
    const float* A = useSeq0 ? g_seq0 : xin;
    __shared__ float As[8][132];
    __shared__ float Bs[8][132];

    const int tid = threadIdx.x;
    const int n0  = blockIdx.x << 7;
    const int m0  = blockIdx.y << 7;
    const int ty  = tid >> 4;
    const int tx  = tid & 15;
    const int r   = tid >> 1;
    const int kc  = (tid & 1) << 2;

    const float* Ap = A   + (size_t)(m0 + r) * K + kc;
    const float* Wp = Wih + (size_t)(n0 + r) * K + kc;

    float acc[8][8] = {};
    const int nch = K >> 3;
    float4 pa = __ldg((const float4*)Ap);
    float4 pw = __ldg((const float4*)Wp);

    for (int ch = 0; ch < nch; ch++) {
        As[kc + 0][r] = pa.x; As[kc + 1][r] = pa.y; As[kc + 2][r] = pa.z; As[kc + 3][r] = pa.w;
        Bs[kc + 0][r] = pw.x; Bs[kc + 1][r] = pw.y; Bs[kc + 2][r] = pw.z; Bs[kc + 3][r] = pw.w;
        __syncthreads();
        if (ch + 1 < nch) {
            pa = __ldg((const float4*)(Ap + (ch + 1) * 8));
            pw = __ldg((const float4*)(Wp + (ch + 1) * 8));
        }
#pragma unroll
        for (int k = 0; k < 8; k++) {
            float4 a0 = *(const float4*)&As[k][ty << 3];
            float4 a1 = *(const float4*)&As[k][(ty << 3) + 4];
            float4 w0 = *(const float4*)&Bs[k][tx << 3];
            float4 w1 = *(const float4*)&Bs[k][(tx << 3) + 4];
            float ar[8] = {a0.x, a0.y, a0.z, a0.w, a1.x, a1.y, a1.z, a1.w};
            float br[8] = {w0.x, w0.y, w0.z, w0.w, w1.x, w1.y, w1.z, w1.w};
#pragma unroll
            for (int i = 0; i < 8; i++)
#pragma unroll
                for (int j = 0; j < 8; j++)
                    acc[i][j] = fmaf(ar[i], br[j], acc[i][j]);
        }
        __syncthreads();
    }

    const int col = n0 + (tx << 3);
    float bias[8];
#pragma unroll
    for (int j = 0; j < 8; j++) bias[j] = __fadd_rn(b0[col + j], b1[col + j]);
#pragma unroll
    for (int i = 0; i < 8; i++) {
        size_t row = (size_t)m0 + (ty << 3) + i;
        float* o = g_gin + row * G4 + col;
#pragma unroll
        for (int j = 0; j < 8; j++) o[j] = __fadd_rn(acc[i][j], bias[j]);
    }
}

// ---------------------------------------------------------------------------------------
// du-dot + state update. 4 threads per row, Eigen-gemv order (4 strided chains, pairwise
// combine). All 16 n-group CTAs of an m-tile compute bit-identical replicated state.
// ---------------------------------------------------------------------------------------
__device__ __forceinline__ void dot_update(
    int parity, int m0, int b, int q4, const float* slw, float lb0v,
    float* su, float* sdu, int* sskip)
{
    const float* nrow = g_ncb[parity] + (size_t)(m0 + b) * HC;
    float a = 0.0f;
    for (int k = q4; k < HC; k += 4)
        a = fmaf(__ldcg(nrow + k), slw[k], a);
    float v1  = __fadd_rn(a,  __shfl_xor_sync(0xffffffffu, a, 1));
    float dot = __fadd_rn(v1, __shfl_xor_sync(0xffffffffu, v1, 2));
    if (q4 == 0) {
        const float uo  = su[b];
        const float duo = sdu[b];
        const int   m   = sskip[b];
        const float bu  = rintf(uo);                       // jnp.round (half-to-even)
        const float omb = __fsub_rn(1.0f, bu);
        float nu, ndu;
        if (!m) {
            float dn = logi_xla(__fadd_rn(dot, lb0v));
            nu = __fmul_rn(dn, bu); ndu = dn;
        } else {
            nu = __fmul_rn(fminf(fmaxf(__fadd_rn(uo, duo), 0.0f), 1.0f), omb);
            ndu = duo;
        }
        su[b] = nu; sdu[b] = ndu;
        sskip[b] = ((__fsub_rn(ceilf(__fdiv_rn(0.5f, nu)), 1.0f)) > 0.0f) ? 1 : 0;
    }
}

// ---------------------------------------------------------------------------------------
// Fused persistent per-layer kernel: ONE grid barrier per step.
// CTA = (m-tile of 32 rows) x (n-group of 16 h-cols, all 4 gates). Gates stay in SMEM;
// c/h-slice/u/du/skip live in SMEM for the whole layer. h and nc double-buffered in L2.
// ---------------------------------------------------------------------------------------
#define WS_ELEMS (256 * 68)
#define HS_ELEMS (256 * 36)
#define DYN_SMEM ((WS_ELEMS + HS_ELEMS) * 4)

__global__ __launch_bounds__(NT, 1) void layer_kernel(
    const float* __restrict__ W,                   // Whh [1024][256]
    const float* __restrict__ lw, const float* __restrict__ lb,
    float* __restrict__ seq_out, int to_seq0,
    float* __restrict__ outH, float* __restrict__ outC)
{
    extern __shared__ float sm[];
    float* Ws = sm;               // [k][64 local gate-cols] pad 68
    float* Hs = sm + WS_ELEMS;    // [k][32 rows] pad 36
    __shared__ float sgates[32 * 68];
    __shared__ float cloc[32 * 16];
    __shared__ float hloc[32 * 16];
    __shared__ float slw[256];
    __shared__ float su[32], sdu[32];
    __shared__ int   sskip[32];

    const int tid   = threadIdx.x;
    const int bid   = blockIdx.x;
    const int ng    = bid & 15;          // n-group: h-cols [16ng, 16ng+16)
    const int m0    = (bid >> 4) * 32;   // m-tile rows
    const int jbase = ng << 4;
    const int ty    = tid >> 4;          // 0..7  (4 rows each)
    const int tx    = tid & 15;          // 0..15 (4 local gate-cols each)
    const int wid   = tid >> 5;
    const int lane  = tid & 31;
    const int pb    = tid >> 2;          // pointwise/dot row 0..31
    const int q4    = tid & 3;           // chain / col-quad index
    const int jl0   = q4 << 2;

    // lw + Whh slab (64 rows: gate g, cols jbase..jbase+15) cached in SMEM, [k][c]
    if (tid < 128) { slw[tid] = lw[tid]; slw[tid + 128] = lw[tid + 128]; }
    const float lb0v = lb[0];
    for (int i = tid; i < 64 * 64; i += NT) {
        int c  = i >> 6;                              // local gate-col 0..63
        int k4 = (i & 63) << 2;
        int grow = (c >> 4) * HC + jbase + (c & 15);  // Whh row (global gate col)
        float4 v = __ldcg((const float4*)(W + (size_t)grow * HC + k4));
        Ws[(k4 + 0) * 68 + c] = v.x; Ws[(k4 + 1) * 68 + c] = v.y;
        Ws[(k4 + 2) * 68 + c] = v.z; Ws[(k4 + 3) * 68 + c] = v.w;
    }

    // local state init (u resets per layer; du/skip carry via globals)
    if (tid < 32) {
        su[tid]    = 1.0f;
        sdu[tid]   = g_du[m0 + tid];
        sskip[tid] = g_skip[m0 + tid];
    }
    for (int i = tid; i < 32 * 16; i += NT) { cloc[i] = 0.0f; hloc[i] = 0.0f; }
    __syncthreads();

    unsigned nbar = 0;

    for (int t = 0; t < T_STEPS; t++) {
        // gin prefetch for this thread's 4x4 gate patch (static data)
        float4 pg[4];
        {
            const int gate = tx >> 2;
            const int gj0  = (tx & 3) << 2;
            const float* gp = g_gin + ((size_t)t * BS + m0 + (ty << 2)) * G4
                              + gate * HC + jbase + gj0;
#pragma unroll
            for (int i = 0; i < 4; i++) pg[i] = __ldcg((const float4*)(gp + (size_t)i * G4));
        }

        // Hs load: h(t) from parity buffer t&1 -> [k][m]
        {
            const float* hsrc = g_h[t & 1];
            for (int i = tid; i < 32 * 64; i += NT) {
                int rr = i >> 6;
                int k4 = (i & 63) << 2;
                float4 v = __ldcg((const float4*)(hsrc + (size_t)(m0 + rr) * HC + k4));
                Hs[(k4 + 0) * 36 + rr] = v.x; Hs[(k4 + 1) * 36 + rr] = v.y;
                Hs[(k4 + 2) * 36 + rr] = v.z; Hs[(k4 + 3) * 36 + rr] = v.w;
            }
        }

        // state update from previous step's nc (parity (t-1)&1)
        if (t > 0) dot_update((t - 1) & 1, m0, pb, q4, slw, lb0v, su, sdu, sskip);
        __syncthreads();

        // GEMM: gates patch (32 rows x 64 local cols) -> sgates (+gin)
        {
            int fl = (lane < 8) ? sskip[(wid << 3) + lane] : 1;
            const bool allskip = __all_sync(0xffffffffu, fl != 0);
            if (!allskip) {
                float acc[4][4] = {};
                const float* hp = &Hs[ty << 2];
                const float* wp = &Ws[tx << 2];
#pragma unroll 8
                for (int k = 0; k < HC; k++) {       // strictly ascending k
                    float4 a = *(const float4*)(hp + k * 36);
                    float4 b = *(const float4*)(wp + k * 68);
                    acc[0][0] = fmaf(a.x, b.x, acc[0][0]); acc[0][1] = fmaf(a.x, b.y, acc[0][1]);
                    acc[0][2] = fmaf(a.x, b.z, acc[0][2]); acc[0][3] = fmaf(a.x, b.w, acc[0][3]);
                    acc[1][0] = fmaf(a.y, b.x, acc[1][0]); acc[1][1] = fmaf(a.y, b.y, acc[1][1]);
                    acc[1][2] = fmaf(a.y, b.z, acc[1][2]); acc[1][3] = fmaf(a.y, b.w, acc[1][3]);
                    acc[2][0] = fmaf(a.z, b.x, acc[2][0]); acc[2][1] = fmaf(a.z, b.y, acc[2][1]);
                    acc[2][2] = fmaf(a.z, b.z, acc[2][2]); acc[2][3] = fmaf(a.z, b.w, acc[2][3]);
                    acc[3][0] = fmaf(a.w, b.x, acc[3][0]); acc[3][1] = fmaf(a.w, b.y, acc[3][1]);
                    acc[3][2] = fmaf(a.w, b.z, acc[3][2]); acc[3][3] = fmaf(a.w, b.w, acc[3][3]);
                }
#pragma unroll
                for (int i = 0; i < 4; i++) {
                    float4 v = make_float4(__fadd_rn(acc[i][0], pg[i].x),
                                           __fadd_rn(acc[i][1], pg[i].y),
                                           __fadd_rn(acc[i][2], pg[i].z),
                                           __fadd_rn(acc[i][3], pg[i].w));
                    *(float4*)&sgates[((ty << 2) + i) * 68 + (tx << 2)] = v;
                }
            }
        }
        __syncthreads();

        // pointwise: 1 row x 4 cols per thread, all CTA-local
        {
            const float uo  = su[pb];
            const int   m   = sskip[pb];
            const float bu  = rintf(uo);
            const float omb = __fsub_rn(1.0f, bu);
            float* cl = cloc + pb * 16 + jl0;
            float* hl = hloc + pb * 16 + jl0;
            float nh[4], nc[4];
            if (!m) {
                const float* sg = sgates + pb * 68;
#pragma unroll
                for (int s = 0; s < 4; s++) {
                    int jl = jl0 + s;
                    float gi = sg[jl], gf = sg[16 + jl], gg = sg[32 + jl], go = sg[48 + jl];
                    float cc = __fadd_rn(__fmul_rn(logi_xla(gf), cl[s]),
                                         __fmul_rn(logi_xla(gi), tanh_xla(gg)));
                    float ch = __fmul_rn(logi_xla(go), tanh_xla(cc));
                    nc[s] = __fmul_rn(cc, bu);
                    nh[s] = __fmul_rn(ch, bu);
                }
            } else {
#pragma unroll
                for (int s = 0; s < 4; s++) {
                    nh[s] = __fmul_rn(hl[s], omb);
                    nc[s] = __fmul_rn(cl[s], omb);
                }
            }
#pragma unroll
            for (int s = 0; s < 4; s++) { cl[s] = nc[s]; hl[s] = nh[s]; }

            const size_t roff = (size_t)(m0 + pb) * HC + jbase + jl0;
            float4 nh4 = make_float4(nh[0], nh[1], nh[2], nh[3]);
            __stcg((float4*)(g_h[(t + 1) & 1] + roff), nh4);      // next-step h buffer
            if (!m) {
                float4 nc4 = make_float4(nc[0], nc[1], nc[2], nc[3]);
                __stcg((float4*)(g_ncb[t & 1] + roff), nc4);      // this-step nc buffer
            }
            float* dp = (to_seq0 ? g_seq0 : seq_out) + (size_t)t * BS * HC + roff;
            __stcg((float4*)dp, nh4);
        }

        grid_sync(nbar);
    }

    // final state update (dot over nc of last step) -> carried du/skip + h/c outputs
    dot_update((T_STEPS - 1) & 1, m0, pb, q4, slw, lb0v, su, sdu, sskip);
    __syncthreads();
    if (ng == 0 && tid < 32) {
        g_du[m0 + tid]   = sdu[tid];
        g_skip[m0 + tid] = sskip[tid];
    }
    {
        const size_t roff = (size_t)(m0 + pb) * HC + jbase + jl0;
        *(float4*)(outH + roff) = *(float4*)(hloc + pb * 16 + jl0);
        *(float4*)(outC + roff) = *(float4*)(cloc + pb * 16 + jl0);
    }
}

// ---------------------------------------------------------------------------------------
__global__ void init0_kernel()   // before layer 0: full reset
{
    int i = blockIdx.x * blockDim.x + threadIdx.x;
    if (i < BS * HC) g_h[0][i] = 0.0f;
    if (i < BS)      { g_du[i] = 0.0f; g_skip[i] = 0; }
    if (i == 0)      g_count = 0u;
}

__global__ void init1_kernel()   // before layer 1: keep carried du/skip
{
    int i = blockIdx.x * blockDim.x + threadIdx.x;
    if (i < BS * HC) g_h[0][i] = 0.0f;
    if (i == 0)      g_count = 0u;
}

// ---------------------------------------------------------------------------------------
extern "C" void kernel_launch(void* const* d_in, const int* in_sizes, int n_in,
                              void* d_out, int out_size)
{
    const float* x    = (const float*)d_in[0];
    const float* Wih0 = (const float*)d_in[1];
    const float* Whh0 = (const float*)d_in[2];
    const float* bih0 = (const float*)d_in[3];
    const float* bhh0 = (const float*)d_in[4];
    const float* lw0  = (const float*)d_in[5];
    const float* lb0  = (const float*)d_in[6];
    const float* Wih1 = (const float*)d_in[7];
    const float* Whh1 = (const float*)d_in[8];
    const float* bih1 = (const float*)d_in[9];
    const float* bhh1 = (const float*)d_in[10];
    const float* lw1  = (const float*)d_in[11];
    const float* lb1  = (const float*)d_in[12];

    float* out   = (float*)d_out;                         // [T, BS, HC]
    float* outHs = out + (size_t)T_STEPS * BS * HC;       // [2, BS, HC]
    float* outCs = outHs + 2 * BS * HC;                   // [2, BS, HC]

    cudaFuncSetAttribute(layer_kernel, cudaFuncAttributeMaxDynamicSharedMemorySize, DYN_SMEM);

    dim3 proj_grid(G4 / 128, (T_STEPS * BS) / 128);       // (8, 1024)

    // launch order keeps layer_kernel as launch #6 (ncu -s 5 -c 1 captures it)
    inproj_kernel<<<proj_grid, 256>>>(x, 0, IC, Wih0, bih0, bhh0);          // 1
    init0_kernel<<<256, 256>>>();                                           // 2
    layer_kernel<<<NB, NT, DYN_SMEM>>>(Whh0, lw0, lb0, nullptr, 1,          // 3
                                       outHs, outCs);
    inproj_kernel<<<proj_grid, 256>>>(nullptr, 1, HC, Wih1, bih1, bhh1);    // 4
    init1_kernel<<<256, 256>>>();                                           // 5
    layer_kernel<<<NB, NT, DYN_SMEM>>>(Whh1, lw1, lb1, out, 0,              // 6
                                       outHs + BS * HC, outCs + BS * HC);
}